// round 1
// baseline (speedup 1.0000x reference)
#include <cuda_runtime.h>

#define NN 50000
#define EE 800000
#define INDIM 256
#define HH 128
#define LLAYERS 4
#define CC 10
#define LN_EPS 1e-5f

// ---------------- scratch (device globals; no allocation) ----------------
__device__ int   d_indeg[2][NN];
__device__ int   d_rowptr[2][NN + 1];
__device__ int   d_cursor[NN];
__device__ float d_dinv[2][NN];
__device__ int   d_ssrc[2][EE];
__device__ float d_x[2][(size_t)NN * HH];
__device__ float d_h[(size_t)NN * HH];

// ---------------- CSR build ----------------
__global__ void k_zero(int s) {
    int i = blockIdx.x * blockDim.x + threadIdx.x;
    if (i < NN) { d_indeg[s][i] = 0; d_cursor[i] = 0; }
}

__global__ void k_hist(const int* __restrict__ dst, int s) {
    int e = blockIdx.x * blockDim.x + threadIdx.x;
    if (e < EE) atomicAdd(&d_indeg[s][dst[e]], 1);
}

// single-block exclusive scan over indeg -> rowptr, plus dinv = rsqrt(indeg+1)
__global__ void k_scan(int s) {
    __shared__ int sh[1024];
    __shared__ int carry;
    int t = threadIdx.x;
    if (t == 0) carry = 0;
    __syncthreads();
    for (int base = 0; base < NN; base += 1024) {
        int i = base + t;
        int v = (i < NN) ? d_indeg[s][i] : 0;
        sh[t] = v;
        __syncthreads();
        #pragma unroll
        for (int off = 1; off < 1024; off <<= 1) {
            int tv = (t >= off) ? sh[t - off] : 0;
            __syncthreads();
            sh[t] += tv;
            __syncthreads();
        }
        int incl = sh[t];
        if (i < NN) {
            d_rowptr[s][i] = carry + incl - v;
            d_dinv[s][i]   = rsqrtf((float)(v + 1));
        }
        __syncthreads();
        if (t == 1023) carry += incl;
        __syncthreads();
    }
    if (t == 0) d_rowptr[s][NN] = carry;
}

__global__ void k_fill(const int* __restrict__ src, const int* __restrict__ dst, int s) {
    int e = blockIdx.x * blockDim.x + threadIdx.x;
    if (e < EE) {
        int d = dst[e];
        int pos = atomicAdd(&d_cursor[d], 1);
        d_ssrc[s][d_rowptr[s][d] + pos] = src[e];
    }
}

// ---------------- SGEMM: C[M x 128] = A[M x K] @ B[K x 128] (+bias) ----------------
template <int K>
__global__ void __launch_bounds__(256) k_gemm(const float* __restrict__ A,
                                              const float* __restrict__ B,
                                              const float* __restrict__ bias,
                                              float* __restrict__ Cmat, int M) {
    constexpr int BM = 128, BN = 128, BK = 16;
    __shared__ float As[BK][BM];
    __shared__ float Bs[BK][BN];
    int tid = threadIdx.x;
    int row0 = blockIdx.x * BM;
    int ty = tid >> 4, tx = tid & 15;

    float acc[8][8];
    #pragma unroll
    for (int i = 0; i < 8; i++)
        #pragma unroll
        for (int j = 0; j < 8; j++) acc[i][j] = 0.f;

    for (int k0 = 0; k0 < K; k0 += BK) {
        #pragma unroll
        for (int l = 0; l < 2; l++) {
            int f = tid + l * 256;          // 512 float4 in A tile
            int ar = f >> 2;                // row in tile (0..127)
            int ac = (f & 3) * 4;           // col (0,4,8,12)
            int grow = row0 + ar;
            float4 v = (grow < M) ? *(const float4*)(A + (size_t)grow * K + k0 + ac)
                                  : make_float4(0.f, 0.f, 0.f, 0.f);
            As[ac + 0][ar] = v.x; As[ac + 1][ar] = v.y;
            As[ac + 2][ar] = v.z; As[ac + 3][ar] = v.w;
        }
        #pragma unroll
        for (int l = 0; l < 2; l++) {
            int f = tid + l * 256;          // 512 float4 in B tile
            int br = f >> 5;                // 0..15
            int bc = (f & 31) * 4;
            *(float4*)&Bs[br][bc] = *(const float4*)(B + (size_t)(k0 + br) * BN + bc);
        }
        __syncthreads();
        #pragma unroll
        for (int k = 0; k < BK; k++) {
            float ra[8], rb[8];
            #pragma unroll
            for (int i = 0; i < 8; i++) ra[i] = As[k][ty * 8 + i];
            #pragma unroll
            for (int j = 0; j < 8; j++) rb[j] = Bs[k][tx * 8 + j];
            #pragma unroll
            for (int i = 0; i < 8; i++)
                #pragma unroll
                for (int j = 0; j < 8; j++) acc[i][j] += ra[i] * rb[j];
        }
        __syncthreads();
    }
    #pragma unroll
    for (int i = 0; i < 8; i++) {
        int grow = row0 + ty * 8 + i;
        if (grow < M) {
            #pragma unroll
            for (int j = 0; j < 8; j += 4) {
                int col = tx * 8 + j;
                float4 v = make_float4(acc[i][j], acc[i][j + 1], acc[i][j + 2], acc[i][j + 3]);
                if (bias) {
                    v.x += bias[col]; v.y += bias[col + 1];
                    v.z += bias[col + 2]; v.w += bias[col + 3];
                }
                *(float4*)(Cmat + (size_t)grow * BN + col) = v;
            }
        }
    }
}

// ---------------- fused GCN aggregate + bias + LayerNorm + ReLU + residual ----------------
// warp per node; 128 channels = 4 per lane
__global__ void __launch_bounds__(256) k_agg(const float* __restrict__ h, int s,
                                             const float* __restrict__ bias,
                                             const float* __restrict__ gamma,
                                             const float* __restrict__ beta,
                                             float* __restrict__ x) {
    int v = (blockIdx.x * blockDim.x + threadIdx.x) >> 5;
    int lane = threadIdx.x & 31;
    if (v >= NN) return;

    float acc0 = 0.f, acc1 = 0.f, acc2 = 0.f, acc3 = 0.f;
    int beg = d_rowptr[s][v], end = d_rowptr[s][v + 1];
    float dv = d_dinv[s][v];

    for (int i = beg; i < end; i++) {
        int u = d_ssrc[s][i];
        float w = d_dinv[s][u];
        const float* hu = h + (size_t)u * HH;
        acc0 += w * hu[lane];
        acc1 += w * hu[lane + 32];
        acc2 += w * hu[lane + 64];
        acc3 += w * hu[lane + 96];
    }
    // self loop
    const float* hv = h + (size_t)v * HH;
    acc0 += dv * hv[lane];
    acc1 += dv * hv[lane + 32];
    acc2 += dv * hv[lane + 64];
    acc3 += dv * hv[lane + 96];

    acc0 = acc0 * dv + bias[lane];
    acc1 = acc1 * dv + bias[lane + 32];
    acc2 = acc2 * dv + bias[lane + 64];
    acc3 = acc3 * dv + bias[lane + 96];

    // layernorm over 128
    float sum = acc0 + acc1 + acc2 + acc3;
    #pragma unroll
    for (int o = 16; o; o >>= 1) sum += __shfl_xor_sync(0xFFFFFFFFu, sum, o);
    float mu = sum * (1.f / HH);
    float v0 = acc0 - mu, v1 = acc1 - mu, v2 = acc2 - mu, v3 = acc3 - mu;
    float var = v0 * v0 + v1 * v1 + v2 * v2 + v3 * v3;
    #pragma unroll
    for (int o = 16; o; o >>= 1) var += __shfl_xor_sync(0xFFFFFFFFu, var, o);
    var *= (1.f / HH);
    float rstd = rsqrtf(var + LN_EPS);

    float* xp = x + (size_t)v * HH;
    float r0 = fmaxf(v0 * rstd * gamma[lane]      + beta[lane],      0.f);
    float r1 = fmaxf(v1 * rstd * gamma[lane + 32] + beta[lane + 32], 0.f);
    float r2 = fmaxf(v2 * rstd * gamma[lane + 64] + beta[lane + 64], 0.f);
    float r3 = fmaxf(v3 * rstd * gamma[lane + 96] + beta[lane + 96], 0.f);
    xp[lane]      += r0;
    xp[lane + 32] += r1;
    xp[lane + 64] += r2;
    xp[lane + 96] += r3;
}

// ---------------- classifier: out[N,10] = concat(xr,xv) @ Wcls + bcls ----------------
__global__ void __launch_bounds__(256) k_cls(const float* __restrict__ xr,
                                             const float* __restrict__ xv,
                                             const float* __restrict__ Wcls,
                                             const float* __restrict__ bcls,
                                             float* __restrict__ out) {
    __shared__ float WsT[CC * 2 * HH];   // [c][k] transposed
    __shared__ float bs[CC];
    for (int i = threadIdx.x; i < 2 * HH * CC; i += blockDim.x) {
        int k = i / CC, c = i % CC;
        WsT[c * (2 * HH) + k] = Wcls[i];
    }
    if (threadIdx.x < CC) bs[threadIdx.x] = bcls[threadIdx.x];
    __syncthreads();

    int v = (blockIdx.x * blockDim.x + threadIdx.x) >> 5;
    int lane = threadIdx.x & 31;
    if (v >= NN) return;

    float acc[CC];
    #pragma unroll
    for (int c = 0; c < CC; c++) acc[c] = 0.f;

    const float* a = xr + (size_t)v * HH;
    const float* b = xv + (size_t)v * HH;
    #pragma unroll
    for (int kk = 0; kk < 4; kk++) {
        int k = lane + 32 * kk;
        float av = a[k];
        float bv = b[k];
        #pragma unroll
        for (int c = 0; c < CC; c++) {
            acc[c] += av * WsT[c * (2 * HH) + k];
            acc[c] += bv * WsT[c * (2 * HH) + 128 + k];
        }
    }
    #pragma unroll
    for (int c = 0; c < CC; c++)
        #pragma unroll
        for (int o = 16; o; o >>= 1) acc[c] += __shfl_xor_sync(0xFFFFFFFFu, acc[c], o);

    if (lane == 0) {
        float* op = out + (size_t)v * CC;
        #pragma unroll
        for (int c = 0; c < CC; c++) op[c] = acc[c] + bs[c];
    }
}

// ---------------- driver ----------------
extern "C" void kernel_launch(void* const* d_in, const int* in_sizes, int n_in,
                              void* d_out, int out_size) {
    const float* x_in[2]  = { (const float*)d_in[0], (const float*)d_in[1] };
    const float* Wred[2]  = { (const float*)d_in[2], (const float*)d_in[4] };
    const float* bred[2]  = { (const float*)d_in[3], (const float*)d_in[5] };
    const float* W[2]     = { (const float*)d_in[6],  (const float*)d_in[10] };
    const float* b[2]     = { (const float*)d_in[7],  (const float*)d_in[11] };
    const float* g[2]     = { (const float*)d_in[8],  (const float*)d_in[12] };
    const float* be[2]    = { (const float*)d_in[9],  (const float*)d_in[13] };
    const float* Wcls     = (const float*)d_in[14];
    const float* bcls     = (const float*)d_in[15];
    const int*   ei[2]    = { (const int*)d_in[16], (const int*)d_in[17] };
    float* out = (float*)d_out;

    void* p;
    cudaGetSymbolAddress(&p, d_x);
    float* px = (float*)p;
    cudaGetSymbolAddress(&p, d_h);
    float* ph = (float*)p;

    const int THR = 256;
    const int blkN_node = (NN + THR - 1) / THR;       // thread-per-node grids
    const int blkE = (EE + THR - 1) / THR;
    const int blkWarp = (NN * 32 + THR - 1) / THR;    // warp-per-node grids
    const int blkGemm = (NN + 127) / 128;

    for (int s = 0; s < 2; s++) {
        const int* src = ei[s];
        const int* dst = ei[s] + EE;
        float* xs = px + (size_t)s * NN * HH;

        k_zero<<<blkN_node, THR>>>(s);
        k_hist<<<blkE, THR>>>(dst, s);
        k_scan<<<1, 1024>>>(s);
        k_fill<<<blkE, THR>>>(src, dst, s);

        // dim reduction: x = x_in @ Wred + bred
        k_gemm<INDIM><<<blkGemm, THR>>>(x_in[s], Wred[s], bred[s], xs, NN);

        for (int l = 0; l < LLAYERS; l++) {
            k_gemm<HH><<<blkGemm, THR>>>(xs, W[s] + (size_t)l * HH * HH, nullptr, ph, NN);
            k_agg<<<blkWarp, THR>>>(ph, s, b[s] + l * HH, g[s] + l * HH, be[s] + l * HH, xs);
        }
    }

    k_cls<<<blkWarp, THR>>>(px, px + (size_t)NN * HH, Wcls, bcls, out);
}

// round 4
// speedup vs baseline: 1.6654x; 1.6654x over previous
#include <cuda_runtime.h>
#include <cuda_bf16.h>
#include <cstdint>

#define NN 50000
#define EE 800000
#define INDIM 256
#define HH 128
#define LLAYERS 4
#define CC 10
#define LN_EPS 1e-5f

// ---------------- scratch (device globals; no allocation) ----------------
__device__ int   d_indeg[2][NN];
__device__ int   d_rowptr[2][NN + 1];
__device__ int   d_cursor[NN];
__device__ float d_dinv[2][NN];
__device__ int   d_ssrc[2][EE];
__device__ float d_x[2][(size_t)NN * HH];
__device__ float d_h[(size_t)NN * HH];
__device__ int   d_blksum[64];

// pre-transposed, bf16-split weights: layout [n][k] (K-major rows of W^T)
__device__ __align__(16) __nv_bfloat16 d_wredT_h[2][HH * INDIM];
__device__ __align__(16) __nv_bfloat16 d_wredT_l[2][HH * INDIM];
__device__ __align__(16) __nv_bfloat16 d_wT_h[2][LLAYERS][HH * HH];
__device__ __align__(16) __nv_bfloat16 d_wT_l[2][LLAYERS][HH * HH];

// ---------------- PTX helpers (sm_80+ only: ldmatrix / mma.sync / cp.async) ----
__device__ __forceinline__ uint32_t smem_u32(const void* p) {
    uint32_t a;
    asm("{ .reg .u64 t; cvta.to.shared.u64 t, %1; cvt.u32.u64 %0, t; }" : "=r"(a) : "l"(p));
    return a;
}

__device__ __forceinline__ void ldsm4(uint32_t* r, uint32_t addr) {
    asm volatile("ldmatrix.sync.aligned.m8n8.x4.shared.b16 {%0,%1,%2,%3}, [%4];"
                 : "=r"(r[0]), "=r"(r[1]), "=r"(r[2]), "=r"(r[3]) : "r"(addr));
}

__device__ __forceinline__ void mma16816(float* d, const uint32_t* a, const uint32_t* b) {
    asm volatile(
        "mma.sync.aligned.m16n8k16.row.col.f32.bf16.bf16.f32 "
        "{%0,%1,%2,%3}, {%4,%5,%6,%7}, {%8,%9}, {%0,%1,%2,%3};"
        : "+f"(d[0]), "+f"(d[1]), "+f"(d[2]), "+f"(d[3])
        : "r"(a[0]), "r"(a[1]), "r"(a[2]), "r"(a[3]), "r"(b[0]), "r"(b[1]));
}

#define CP_ASYNC16(dst, src) \
    asm volatile("cp.async.cg.shared.global [%0], [%1], 16;" :: "r"(dst), "l"(src))
#define CP_COMMIT() asm volatile("cp.async.commit_group;")
#define CP_WAIT0()  asm volatile("cp.async.wait_group 0;" ::: "memory")

// ---------------- CSR build ----------------
__global__ void k_zero(int s) {
    int i = blockIdx.x * blockDim.x + threadIdx.x;
    if (i < NN) { d_indeg[s][i] = 0; d_cursor[i] = 0; }
}

__global__ void k_hist(const int* __restrict__ dst, int s) {
    int e = blockIdx.x * blockDim.x + threadIdx.x;
    if (e < EE) atomicAdd(&d_indeg[s][dst[e]], 1);
}

__global__ void k_scan1(int s) {
    __shared__ int sh[1024];
    int b = blockIdx.x, t = threadIdx.x, i = b * 1024 + t;
    int v = (i < NN) ? d_indeg[s][i] : 0;
    sh[t] = v;
    __syncthreads();
    #pragma unroll
    for (int off = 1; off < 1024; off <<= 1) {
        int x = (t >= off) ? sh[t - off] : 0;
        __syncthreads();
        sh[t] += x;
        __syncthreads();
    }
    if (i < NN) {
        d_rowptr[s][i] = sh[t] - v;
        d_dinv[s][i]   = rsqrtf((float)(v + 1));
    }
    if (t == 1023) d_blksum[b] = sh[t];
}

__global__ void k_scan2() {
    __shared__ int sh[64];
    int t = threadIdx.x;
    int v = (t < 49) ? d_blksum[t] : 0;
    sh[t] = v;
    __syncthreads();
    #pragma unroll
    for (int off = 1; off < 64; off <<= 1) {
        int x = (t >= off) ? sh[t - off] : 0;
        __syncthreads();
        sh[t] += x;
        __syncthreads();
    }
    if (t < 49) d_blksum[t] = sh[t] - v;
}

__global__ void k_scan3(int s) {
    int b = blockIdx.x, i = b * 1024 + threadIdx.x;
    if (i < NN) d_rowptr[s][i] += d_blksum[b];
    if (i == 0) d_rowptr[s][NN] = EE;
}

__global__ void k_fill(const int* __restrict__ src, const int* __restrict__ dst, int s) {
    int e = blockIdx.x * blockDim.x + threadIdx.x;
    if (e < EE) {
        int d = dst[e];
        int pos = atomicAdd(&d_cursor[d], 1);
        d_ssrc[s][d_rowptr[s][d] + pos] = src[e];
    }
}

// ---------------- weight prep: transpose + bf16 hi/lo split ----------------
__global__ void k_prep(const float* __restrict__ Wred0, const float* __restrict__ Wred1,
                       const float* __restrict__ W0, const float* __restrict__ W1) {
    const int PER_STREAM = INDIM * HH + LLAYERS * HH * HH;
    int i = blockIdx.x * blockDim.x + threadIdx.x;
    if (i >= 2 * PER_STREAM) return;
    int s = i >= PER_STREAM;
    int j = i - s * PER_STREAM;
    float w;
    __nv_bfloat16 *ph, *pl;
    if (j < INDIM * HH) {
        int k = j >> 7, n = j & 127;
        w = (s ? Wred1 : Wred0)[k * HH + n];
        ph = &d_wredT_h[s][n * INDIM + k];
        pl = &d_wredT_l[s][n * INDIM + k];
    } else {
        int r = j - INDIM * HH;
        int l = r >> 14;
        int k = (r >> 7) & 127, n = r & 127;
        w = (s ? W1 : W0)[l * HH * HH + k * HH + n];
        ph = &d_wT_h[s][l][n * HH + k];
        pl = &d_wT_l[s][l][n * HH + k];
    }
    __nv_bfloat16 h = __float2bfloat16(w);
    *ph = h;
    *pl = __float2bfloat16(w - __bfloat162float(h));
}

// ---------------- mma.sync bf16 GEMM (3-pass compensated): C = A @ Bt^T (+bias) ----
// A: [M x KTOT] fp32 (split in-kernel). Bh/Bl: [128 (n)] x [KTOT (k)] bf16.
// CTA tile 128x128, BK=32, 8 warps each 32(m) x 64(n).
template <int KTOT>
__global__ void __launch_bounds__(256) k_gemm_mma(
    const float* __restrict__ A,
    const __nv_bfloat16* __restrict__ Bh,
    const __nv_bfloat16* __restrict__ Bl,
    const float* __restrict__ bias,
    float* __restrict__ C, int M)
{
    constexpr int RS = 80;                 // padded row stride (bytes): 32 bf16 + 16B pad
    __shared__ __align__(16) char smem[4 * 128 * RS];   // 40960B
    const uint32_t AS_H = smem_u32(smem);
    const uint32_t AS_L = AS_H + 128 * RS;
    const uint32_t BS_H = AS_H + 2 * 128 * RS;
    const uint32_t BS_L = AS_H + 3 * 128 * RS;

    int tid = threadIdx.x, w = tid >> 5, lane = tid & 31;
    int row0 = blockIdx.x * 128;
    int wm = (w >> 1) * 32, wn = (w & 1) * 64;

    float acc[2][8][4];
    #pragma unroll
    for (int i = 0; i < 2; i++)
        #pragma unroll
        for (int j = 0; j < 8; j++)
            #pragma unroll
            for (int q = 0; q < 4; q++) acc[i][j][q] = 0.f;

    // loader assignment: thread t -> row = t/2, k-half = t&1 (16 elements)
    int lrow = tid >> 1, lhalf = tid & 1;
    bool avalid = (row0 + lrow) < M;
    const float* aptr = A + (size_t)(row0 + lrow) * KTOT + lhalf * 16;
    const __nv_bfloat16* bhp = Bh + (size_t)lrow * KTOT + lhalf * 16;
    const __nv_bfloat16* blp = Bl + (size_t)lrow * KTOT + lhalf * 16;
    uint32_t ash_st = AS_H + lrow * RS + lhalf * 32;
    uint32_t asl_st = AS_L + lrow * RS + lhalf * 32;
    uint32_t bsh_st = BS_H + lrow * RS + lhalf * 32;
    uint32_t bsl_st = BS_L + lrow * RS + lhalf * 32;

    // ldmatrix base offsets (per lane)
    int a_r = lane & 15, a_k = (lane >> 4) * 8;                       // A: rows, k-half
    int b_r = ((lane >> 4) << 3) + (lane & 7), b_k = ((lane >> 3) & 1) * 8;  // B

    for (int c0 = 0; c0 < KTOT; c0 += 32) {
        // --- B tile via cp.async (bf16, pre-split) ---
        CP_ASYNC16(bsh_st,      bhp);
        CP_ASYNC16(bsh_st + 16, bhp + 8);
        CP_ASYNC16(bsl_st,      blp);
        CP_ASYNC16(bsl_st + 16, blp + 8);
        CP_COMMIT();
        bhp += 32; blp += 32;

        // --- A tile: fp32 load -> hi/lo bf16 split -> smem ---
        float xv[16];
        if (avalid) {
            #pragma unroll
            for (int g = 0; g < 4; g++) {
                float4 v = *(const float4*)(aptr + g * 4);
                xv[g * 4] = v.x; xv[g * 4 + 1] = v.y; xv[g * 4 + 2] = v.z; xv[g * 4 + 3] = v.w;
            }
        } else {
            #pragma unroll
            for (int j = 0; j < 16; j++) xv[j] = 0.f;
        }
        aptr += 32;
        union { uint4 q[2]; __nv_bfloat16 b[16]; } hi, lo;
        #pragma unroll
        for (int j = 0; j < 16; j++) {
            __nv_bfloat16 h = __float2bfloat16(xv[j]);
            hi.b[j] = h;
            lo.b[j] = __float2bfloat16(xv[j] - __bfloat162float(h));
        }
        asm volatile("st.shared.v4.b32 [%0], {%1,%2,%3,%4};" :: "r"(ash_st),
            "r"(hi.q[0].x), "r"(hi.q[0].y), "r"(hi.q[0].z), "r"(hi.q[0].w));
        asm volatile("st.shared.v4.b32 [%0], {%1,%2,%3,%4};" :: "r"(ash_st + 16),
            "r"(hi.q[1].x), "r"(hi.q[1].y), "r"(hi.q[1].z), "r"(hi.q[1].w));
        asm volatile("st.shared.v4.b32 [%0], {%1,%2,%3,%4};" :: "r"(asl_st),
            "r"(lo.q[0].x), "r"(lo.q[0].y), "r"(lo.q[0].z), "r"(lo.q[0].w));
        asm volatile("st.shared.v4.b32 [%0], {%1,%2,%3,%4};" :: "r"(asl_st + 16),
            "r"(lo.q[1].x), "r"(lo.q[1].y), "r"(lo.q[1].z), "r"(lo.q[1].w));

        CP_WAIT0();
        __syncthreads();

        // --- compute 2 k16-steps ---
        #pragma unroll
        for (int ks = 0; ks < 2; ks++) {
            int kb = ks * 16;
            uint32_t ah[2][4], al[2][4];
            #pragma unroll
            for (int mt = 0; mt < 2; mt++) {
                uint32_t off = (uint32_t)((wm + mt * 16 + a_r) * RS + (kb + a_k) * 2);
                ldsm4(ah[mt], AS_H + off);
                ldsm4(al[mt], AS_L + off);
            }
            uint32_t bh[4][4], bl[4][4];
            #pragma unroll
            for (int nt = 0; nt < 4; nt++) {
                uint32_t off = (uint32_t)((wn + nt * 16 + b_r) * RS + (kb + b_k) * 2);
                ldsm4(bh[nt], BS_H + off);
                ldsm4(bl[nt], BS_L + off);
            }
            #pragma unroll
            for (int mt = 0; mt < 2; mt++) {
                #pragma unroll
                for (int j = 0; j < 8; j++) {
                    const uint32_t* ph = &bh[j >> 1][(j & 1) * 2];
                    const uint32_t* pl = &bl[j >> 1][(j & 1) * 2];
                    mma16816(acc[mt][j], ah[mt], ph);   // hh
                    mma16816(acc[mt][j], ah[mt], pl);   // hl
                    mma16816(acc[mt][j], al[mt], ph);   // lh
                }
            }
        }
        __syncthreads();
    }

    // --- epilogue ---
    int qr = lane >> 2, qc = (lane & 3) * 2;
    #pragma unroll
    for (int mt = 0; mt < 2; mt++) {
        int r0g = row0 + wm + mt * 16 + qr;
        #pragma unroll
        for (int j = 0; j < 8; j++) {
            int col = wn + j * 8 + qc;
            float b0 = 0.f, b1 = 0.f;
            if (bias) { b0 = bias[col]; b1 = bias[col + 1]; }
            if (r0g < M)
                *(float2*)(C + (size_t)r0g * HH + col) =
                    make_float2(acc[mt][j][0] + b0, acc[mt][j][1] + b1);
            if (r0g + 8 < M)
                *(float2*)(C + (size_t)(r0g + 8) * HH + col) =
                    make_float2(acc[mt][j][2] + b0, acc[mt][j][3] + b1);
        }
    }
}

// ---------------- fused GCN aggregate + bias + LayerNorm + ReLU + residual ----------------
__global__ void __launch_bounds__(256) k_agg(const float* __restrict__ h, int s,
                                             const float* __restrict__ bias,
                                             const float* __restrict__ gamma,
                                             const float* __restrict__ beta,
                                             float* __restrict__ x) {
    int v = (blockIdx.x * blockDim.x + threadIdx.x) >> 5;
    int lane = threadIdx.x & 31;
    if (v >= NN) return;

    float acc0 = 0.f, acc1 = 0.f, acc2 = 0.f, acc3 = 0.f;
    float bcc0 = 0.f, bcc1 = 0.f, bcc2 = 0.f, bcc3 = 0.f;
    int beg = d_rowptr[s][v], end = d_rowptr[s][v + 1];
    float dv = d_dinv[s][v];

    int i = beg;
    for (; i + 2 <= end; i += 2) {
        int u0 = d_ssrc[s][i];
        int u1 = d_ssrc[s][i + 1];
        float w0 = d_dinv[s][u0];
        float w1 = d_dinv[s][u1];
        const float* h0 = h + (size_t)u0 * HH;
        const float* h1 = h + (size_t)u1 * HH;
        acc0 += w0 * h0[lane];       bcc0 += w1 * h1[lane];
        acc1 += w0 * h0[lane + 32];  bcc1 += w1 * h1[lane + 32];
        acc2 += w0 * h0[lane + 64];  bcc2 += w1 * h1[lane + 64];
        acc3 += w0 * h0[lane + 96];  bcc3 += w1 * h1[lane + 96];
    }
    if (i < end) {
        int u = d_ssrc[s][i];
        float w = d_dinv[s][u];
        const float* hu = h + (size_t)u * HH;
        acc0 += w * hu[lane];
        acc1 += w * hu[lane + 32];
        acc2 += w * hu[lane + 64];
        acc3 += w * hu[lane + 96];
    }
    const float* hv = h + (size_t)v * HH;
    acc0 += bcc0 + dv * hv[lane];
    acc1 += bcc1 + dv * hv[lane + 32];
    acc2 += bcc2 + dv * hv[lane + 64];
    acc3 += bcc3 + dv * hv[lane + 96];

    acc0 = acc0 * dv + bias[lane];
    acc1 = acc1 * dv + bias[lane + 32];
    acc2 = acc2 * dv + bias[lane + 64];
    acc3 = acc3 * dv + bias[lane + 96];

    float sum = acc0 + acc1 + acc2 + acc3;
    #pragma unroll
    for (int o = 16; o; o >>= 1) sum += __shfl_xor_sync(0xFFFFFFFFu, sum, o);
    float mu = sum * (1.f / HH);
    float v0 = acc0 - mu, v1 = acc1 - mu, v2 = acc2 - mu, v3 = acc3 - mu;
    float var = v0 * v0 + v1 * v1 + v2 * v2 + v3 * v3;
    #pragma unroll
    for (int o = 16; o; o >>= 1) var += __shfl_xor_sync(0xFFFFFFFFu, var, o);
    var *= (1.f / HH);
    float rstd = rsqrtf(var + LN_EPS);

    float* xp = x + (size_t)v * HH;
    xp[lane]      += fmaxf(v0 * rstd * gamma[lane]      + beta[lane],      0.f);
    xp[lane + 32] += fmaxf(v1 * rstd * gamma[lane + 32] + beta[lane + 32], 0.f);
    xp[lane + 64] += fmaxf(v2 * rstd * gamma[lane + 64] + beta[lane + 64], 0.f);
    xp[lane + 96] += fmaxf(v3 * rstd * gamma[lane + 96] + beta[lane + 96], 0.f);
}

// ---------------- classifier ----------------
__global__ void __launch_bounds__(256) k_cls(const float* __restrict__ xr,
                                             const float* __restrict__ xv,
                                             const float* __restrict__ Wcls,
                                             const float* __restrict__ bcls,
                                             float* __restrict__ out) {
    __shared__ float WsT[CC * 2 * HH];
    __shared__ float bs[CC];
    for (int i = threadIdx.x; i < 2 * HH * CC; i += blockDim.x) {
        int k = i / CC, c = i % CC;
        WsT[c * (2 * HH) + k] = Wcls[i];
    }
    if (threadIdx.x < CC) bs[threadIdx.x] = bcls[threadIdx.x];
    __syncthreads();

    int v = (blockIdx.x * blockDim.x + threadIdx.x) >> 5;
    int lane = threadIdx.x & 31;
    if (v >= NN) return;

    float acc[CC];
    #pragma unroll
    for (int c = 0; c < CC; c++) acc[c] = 0.f;

    const float* a = xr + (size_t)v * HH;
    const float* b = xv + (size_t)v * HH;
    #pragma unroll
    for (int kk = 0; kk < 4; kk++) {
        int k = lane + 32 * kk;
        float av = a[k];
        float bv = b[k];
        #pragma unroll
        for (int c = 0; c < CC; c++) {
            acc[c] += av * WsT[c * (2 * HH) + k];
            acc[c] += bv * WsT[c * (2 * HH) + 128 + k];
        }
    }
    #pragma unroll
    for (int c = 0; c < CC; c++)
        #pragma unroll
        for (int o = 16; o; o >>= 1) acc[c] += __shfl_xor_sync(0xFFFFFFFFu, acc[c], o);

    if (lane == 0) {
        float* op = out + (size_t)v * CC;
        #pragma unroll
        for (int c = 0; c < CC; c++) op[c] = acc[c] + bs[c];
    }
}

// ---------------- driver ----------------
extern "C" void kernel_launch(void* const* d_in, const int* in_sizes, int n_in,
                              void* d_out, int out_size) {
    const float* x_in[2]  = { (const float*)d_in[0], (const float*)d_in[1] };
    const float* Wred[2]  = { (const float*)d_in[2], (const float*)d_in[4] };
    const float* bred[2]  = { (const float*)d_in[3], (const float*)d_in[5] };
    const float* W[2]     = { (const float*)d_in[6],  (const float*)d_in[10] };
    const float* b[2]     = { (const float*)d_in[7],  (const float*)d_in[11] };
    const float* g[2]     = { (const float*)d_in[8],  (const float*)d_in[12] };
    const float* be[2]    = { (const float*)d_in[9],  (const float*)d_in[13] };
    const float* Wcls     = (const float*)d_in[14];
    const float* bcls     = (const float*)d_in[15];
    const int*   ei[2]    = { (const int*)d_in[16], (const int*)d_in[17] };
    float* out = (float*)d_out;

    void* p;
    cudaGetSymbolAddress(&p, d_x);
    float* px = (float*)p;
    cudaGetSymbolAddress(&p, d_h);
    float* ph = (float*)p;
    __nv_bfloat16 *wredT_h, *wredT_l, *wT_h, *wT_l;
    cudaGetSymbolAddress(&p, d_wredT_h); wredT_h = (__nv_bfloat16*)p;
    cudaGetSymbolAddress(&p, d_wredT_l); wredT_l = (__nv_bfloat16*)p;
    cudaGetSymbolAddress(&p, d_wT_h);    wT_h    = (__nv_bfloat16*)p;
    cudaGetSymbolAddress(&p, d_wT_l);    wT_l    = (__nv_bfloat16*)p;

    const int THR = 256;
    const int blkN_node = (NN + THR - 1) / THR;
    const int blkE = (EE + THR - 1) / THR;
    const int blkWarp = (NN * 32 + THR - 1) / THR;
    const int blkGemm = (NN + 127) / 128;
    const int blkScan = (NN + 1023) / 1024;   // 49

    {
        const int TOT = 2 * (INDIM * HH + LLAYERS * HH * HH);
        k_prep<<<(TOT + THR - 1) / THR, THR>>>(Wred[0], Wred[1], W[0], W[1]);
    }

    for (int s = 0; s < 2; s++) {
        const int* src = ei[s];
        const int* dst = ei[s] + EE;
        float* xs = px + (size_t)s * NN * HH;

        k_zero<<<blkN_node, THR>>>(s);
        k_hist<<<blkE, THR>>>(dst, s);
        k_scan1<<<blkScan, 1024>>>(s);
        k_scan2<<<1, 64>>>();
        k_scan3<<<blkScan, 1024>>>(s);
        k_fill<<<blkE, THR>>>(src, dst, s);

        k_gemm_mma<INDIM><<<blkGemm, 256>>>(
            x_in[s], wredT_h + (size_t)s * HH * INDIM, wredT_l + (size_t)s * HH * INDIM,
            bred[s], xs, NN);

        for (int l = 0; l < LLAYERS; l++) {
            k_gemm_mma<HH><<<blkGemm, 256>>>(
                xs,
                wT_h + ((size_t)s * LLAYERS + l) * HH * HH,
                wT_l + ((size_t)s * LLAYERS + l) * HH * HH,
                nullptr, ph, NN);
            k_agg<<<blkWarp, THR>>>(ph, s, b[s] + l * HH, g[s] + l * HH, be[s] + l * HH, xs);
        }
    }

    k_cls<<<blkWarp, THR>>>(px, px + (size_t)NN * HH, Wcls, bcls, out);
}

// round 5
// speedup vs baseline: 1.7254x; 1.0360x over previous
#include <cuda_runtime.h>
#include <cuda_bf16.h>
#include <cuda_fp16.h>
#include <cstdint>

#define NN 50000
#define EE 800000
#define INDIM 256
#define HH 128
#define LLAYERS 4
#define CC 10
#define LN_EPS 1e-5f

// ---------------- scratch (device globals; no allocation) ----------------
__device__ int   d_indeg[2][NN];
__device__ int   d_rowptr[2][NN + 1];
__device__ int   d_cursor[NN];
__device__ float d_dinv[2][NN];
__device__ int   d_ssrc[2][EE];
__device__ float d_x[2][(size_t)NN * HH];
__device__ __align__(16) __half d_h[(size_t)NN * HH];
__device__ int   d_blksum[64];

// pre-transposed, bf16-split weights: layout [n][k] (K-major rows of W^T)
__device__ __align__(16) __nv_bfloat16 d_wredT_h[2][HH * INDIM];
__device__ __align__(16) __nv_bfloat16 d_wredT_l[2][HH * INDIM];
__device__ __align__(16) __nv_bfloat16 d_wT_h[2][LLAYERS][HH * HH];
__device__ __align__(16) __nv_bfloat16 d_wT_l[2][LLAYERS][HH * HH];

// ---------------- PTX helpers (sm_80+ only: ldmatrix / mma.sync / cp.async) ----
__device__ __forceinline__ uint32_t smem_u32(const void* p) {
    uint32_t a;
    asm("{ .reg .u64 t; cvta.to.shared.u64 t, %1; cvt.u32.u64 %0, t; }" : "=r"(a) : "l"(p));
    return a;
}

__device__ __forceinline__ void ldsm4(uint32_t* r, uint32_t addr) {
    asm volatile("ldmatrix.sync.aligned.m8n8.x4.shared.b16 {%0,%1,%2,%3}, [%4];"
                 : "=r"(r[0]), "=r"(r[1]), "=r"(r[2]), "=r"(r[3]) : "r"(addr));
}

__device__ __forceinline__ void mma16816(float* d, const uint32_t* a, const uint32_t* b) {
    asm volatile(
        "mma.sync.aligned.m16n8k16.row.col.f32.bf16.bf16.f32 "
        "{%0,%1,%2,%3}, {%4,%5,%6,%7}, {%8,%9}, {%0,%1,%2,%3};"
        : "+f"(d[0]), "+f"(d[1]), "+f"(d[2]), "+f"(d[3])
        : "r"(a[0]), "r"(a[1]), "r"(a[2]), "r"(a[3]), "r"(b[0]), "r"(b[1]));
}

#define CP_ASYNC16(dst, src) \
    asm volatile("cp.async.cg.shared.global [%0], [%1], 16;" :: "r"(dst), "l"(src))
#define CP_COMMIT() asm volatile("cp.async.commit_group;")
#define CP_WAIT0()  asm volatile("cp.async.wait_group 0;" ::: "memory")

// ---------------- CSR build ----------------
__global__ void k_zero(int s) {
    int i = blockIdx.x * blockDim.x + threadIdx.x;
    if (i < NN) d_indeg[s][i] = 0;
}

__global__ void k_hist(const int* __restrict__ dst, int s) {
    int e = blockIdx.x * blockDim.x + threadIdx.x;
    if (e < EE) atomicAdd(&d_indeg[s][dst[e]], 1);
}

__global__ void k_scan1(int s) {
    __shared__ int sh[1024];
    int b = blockIdx.x, t = threadIdx.x, i = b * 1024 + t;
    int v = (i < NN) ? d_indeg[s][i] : 0;
    sh[t] = v;
    __syncthreads();
    #pragma unroll
    for (int off = 1; off < 1024; off <<= 1) {
        int x = (t >= off) ? sh[t - off] : 0;
        __syncthreads();
        sh[t] += x;
        __syncthreads();
    }
    if (i < NN) {
        d_rowptr[s][i] = sh[t] - v;
        d_dinv[s][i]   = rsqrtf((float)(v + 1));
    }
    if (t == 1023) d_blksum[b] = sh[t];
}

__global__ void k_scan2() {
    __shared__ int sh[64];
    int t = threadIdx.x;
    int v = (t < 49) ? d_blksum[t] : 0;
    sh[t] = v;
    __syncthreads();
    #pragma unroll
    for (int off = 1; off < 64; off <<= 1) {
        int x = (t >= off) ? sh[t - off] : 0;
        __syncthreads();
        sh[t] += x;
        __syncthreads();
    }
    if (t < 49) d_blksum[t] = sh[t] - v;
}

__global__ void k_scan3(int s) {
    int b = blockIdx.x, i = b * 1024 + threadIdx.x;
    if (i < NN) {
        int r = d_rowptr[s][i] + d_blksum[b];
        d_rowptr[s][i] = r;
        d_cursor[i] = r;                  // seed cursor with rowptr
    }
    if (i == 0) d_rowptr[s][NN] = EE;
}

__global__ void k_fill(const int* __restrict__ src, const int* __restrict__ dst, int s) {
    int e = blockIdx.x * blockDim.x + threadIdx.x;
    if (e < EE) {
        int pos = atomicAdd(&d_cursor[dst[e]], 1);
        d_ssrc[s][pos] = src[e];
    }
}

// ---------------- weight prep: transpose + bf16 hi/lo split ----------------
__global__ void k_prep(const float* __restrict__ Wred0, const float* __restrict__ Wred1,
                       const float* __restrict__ W0, const float* __restrict__ W1) {
    const int PER_STREAM = INDIM * HH + LLAYERS * HH * HH;
    int i = blockIdx.x * blockDim.x + threadIdx.x;
    if (i >= 2 * PER_STREAM) return;
    int s = i >= PER_STREAM;
    int j = i - s * PER_STREAM;
    float w;
    __nv_bfloat16 *ph, *pl;
    if (j < INDIM * HH) {
        int k = j >> 7, n = j & 127;
        w = (s ? Wred1 : Wred0)[k * HH + n];
        ph = &d_wredT_h[s][n * INDIM + k];
        pl = &d_wredT_l[s][n * INDIM + k];
    } else {
        int r = j - INDIM * HH;
        int l = r >> 14;
        int k = (r >> 7) & 127, n = r & 127;
        w = (s ? W1 : W0)[l * HH * HH + k * HH + n];
        ph = &d_wT_h[s][l][n * HH + k];
        pl = &d_wT_l[s][l][n * HH + k];
    }
    __nv_bfloat16 h = __float2bfloat16(w);
    *ph = h;
    *pl = __float2bfloat16(w - __bfloat162float(h));
}

// ---------------- mma.sync bf16 GEMM (3-pass compensated): C = A @ Bt^T (+bias) ----
// A: [M x KTOT] fp32 (split in-kernel). Bh/Bl: [128 (n)] x [KTOT (k)] bf16.
// CTA tile 128x128, BK=32, 8 warps each 32(m) x 64(n). HOUT: store C as fp16.
template <int KTOT, bool HOUT>
__global__ void __launch_bounds__(256) k_gemm_mma(
    const float* __restrict__ A,
    const __nv_bfloat16* __restrict__ Bh,
    const __nv_bfloat16* __restrict__ Bl,
    const float* __restrict__ bias,
    void* __restrict__ Cout, int M)
{
    constexpr int RS = 80;                 // padded row stride (bytes)
    __shared__ __align__(16) char smem[4 * 128 * RS];
    const uint32_t AS_H = smem_u32(smem);
    const uint32_t AS_L = AS_H + 128 * RS;
    const uint32_t BS_H = AS_H + 2 * 128 * RS;
    const uint32_t BS_L = AS_H + 3 * 128 * RS;

    int tid = threadIdx.x, w = tid >> 5, lane = tid & 31;
    int row0 = blockIdx.x * 128;
    int wm = (w >> 1) * 32, wn = (w & 1) * 64;

    float acc[2][8][4];
    #pragma unroll
    for (int i = 0; i < 2; i++)
        #pragma unroll
        for (int j = 0; j < 8; j++)
            #pragma unroll
            for (int q = 0; q < 4; q++) acc[i][j][q] = 0.f;

    int lrow = tid >> 1, lhalf = tid & 1;
    bool avalid = (row0 + lrow) < M;
    const float* aptr = A + (size_t)(row0 + lrow) * KTOT + lhalf * 16;
    const __nv_bfloat16* bhp = Bh + (size_t)lrow * KTOT + lhalf * 16;
    const __nv_bfloat16* blp = Bl + (size_t)lrow * KTOT + lhalf * 16;
    uint32_t ash_st = AS_H + lrow * RS + lhalf * 32;
    uint32_t asl_st = AS_L + lrow * RS + lhalf * 32;
    uint32_t bsh_st = BS_H + lrow * RS + lhalf * 32;
    uint32_t bsl_st = BS_L + lrow * RS + lhalf * 32;

    int a_r = lane & 15, a_k = (lane >> 4) * 8;
    int b_r = ((lane >> 4) << 3) + (lane & 7), b_k = ((lane >> 3) & 1) * 8;

    for (int c0 = 0; c0 < KTOT; c0 += 32) {
        CP_ASYNC16(bsh_st,      bhp);
        CP_ASYNC16(bsh_st + 16, bhp + 8);
        CP_ASYNC16(bsl_st,      blp);
        CP_ASYNC16(bsl_st + 16, blp + 8);
        CP_COMMIT();
        bhp += 32; blp += 32;

        float xv[16];
        if (avalid) {
            #pragma unroll
            for (int g = 0; g < 4; g++) {
                float4 v = *(const float4*)(aptr + g * 4);
                xv[g * 4] = v.x; xv[g * 4 + 1] = v.y; xv[g * 4 + 2] = v.z; xv[g * 4 + 3] = v.w;
            }
        } else {
            #pragma unroll
            for (int j = 0; j < 16; j++) xv[j] = 0.f;
        }
        aptr += 32;
        union { uint4 q[2]; __nv_bfloat16 b[16]; } hi, lo;
        #pragma unroll
        for (int j = 0; j < 16; j++) {
            __nv_bfloat16 h = __float2bfloat16(xv[j]);
            hi.b[j] = h;
            lo.b[j] = __float2bfloat16(xv[j] - __bfloat162float(h));
        }
        asm volatile("st.shared.v4.b32 [%0], {%1,%2,%3,%4};" :: "r"(ash_st),
            "r"(hi.q[0].x), "r"(hi.q[0].y), "r"(hi.q[0].z), "r"(hi.q[0].w));
        asm volatile("st.shared.v4.b32 [%0], {%1,%2,%3,%4};" :: "r"(ash_st + 16),
            "r"(hi.q[1].x), "r"(hi.q[1].y), "r"(hi.q[1].z), "r"(hi.q[1].w));
        asm volatile("st.shared.v4.b32 [%0], {%1,%2,%3,%4};" :: "r"(asl_st),
            "r"(lo.q[0].x), "r"(lo.q[0].y), "r"(lo.q[0].z), "r"(lo.q[0].w));
        asm volatile("st.shared.v4.b32 [%0], {%1,%2,%3,%4};" :: "r"(asl_st + 16),
            "r"(lo.q[1].x), "r"(lo.q[1].y), "r"(lo.q[1].z), "r"(lo.q[1].w));

        CP_WAIT0();
        __syncthreads();

        #pragma unroll
        for (int ks = 0; ks < 2; ks++) {
            int kb = ks * 16;
            uint32_t ah[2][4], al[2][4];
            #pragma unroll
            for (int mt = 0; mt < 2; mt++) {
                uint32_t off = (uint32_t)((wm + mt * 16 + a_r) * RS + (kb + a_k) * 2);
                ldsm4(ah[mt], AS_H + off);
                ldsm4(al[mt], AS_L + off);
            }
            uint32_t bh[4][4], bl[4][4];
            #pragma unroll
            for (int nt = 0; nt < 4; nt++) {
                uint32_t off = (uint32_t)((wn + nt * 16 + b_r) * RS + (kb + b_k) * 2);
                ldsm4(bh[nt], BS_H + off);
                ldsm4(bl[nt], BS_L + off);
            }
            #pragma unroll
            for (int mt = 0; mt < 2; mt++) {
                #pragma unroll
                for (int j = 0; j < 8; j++) {
                    const uint32_t* ph = &bh[j >> 1][(j & 1) * 2];
                    const uint32_t* pl = &bl[j >> 1][(j & 1) * 2];
                    mma16816(acc[mt][j], ah[mt], ph);
                    mma16816(acc[mt][j], ah[mt], pl);
                    mma16816(acc[mt][j], al[mt], ph);
                }
            }
        }
        __syncthreads();
    }

    // --- epilogue ---
    int qr = lane >> 2, qc = (lane & 3) * 2;
    #pragma unroll
    for (int mt = 0; mt < 2; mt++) {
        int r0g = row0 + wm + mt * 16 + qr;
        #pragma unroll
        for (int j = 0; j < 8; j++) {
            int col = wn + j * 8 + qc;
            float b0 = 0.f, b1 = 0.f;
            if (bias) { b0 = bias[col]; b1 = bias[col + 1]; }
            if (HOUT) {
                __half* Ch = (__half*)Cout;
                if (r0g < M)
                    *(__half2*)(Ch + (size_t)r0g * HH + col) =
                        __floats2half2_rn(acc[mt][j][0] + b0, acc[mt][j][1] + b1);
                if (r0g + 8 < M)
                    *(__half2*)(Ch + (size_t)(r0g + 8) * HH + col) =
                        __floats2half2_rn(acc[mt][j][2] + b0, acc[mt][j][3] + b1);
            } else {
                float* Cf = (float*)Cout;
                if (r0g < M)
                    *(float2*)(Cf + (size_t)r0g * HH + col) =
                        make_float2(acc[mt][j][0] + b0, acc[mt][j][1] + b1);
                if (r0g + 8 < M)
                    *(float2*)(Cf + (size_t)(r0g + 8) * HH + col) =
                        make_float2(acc[mt][j][2] + b0, acc[mt][j][3] + b1);
            }
        }
    }
}

// ---------------- fused GCN aggregate + bias + LayerNorm + ReLU + residual ----------------
// warp per node; h in fp16. Lane owns channels {2L, 2L+1, 64+2L, 64+2L+1}.
__global__ void __launch_bounds__(256) k_agg(const __half* __restrict__ h, int s,
                                             const float* __restrict__ bias,
                                             const float* __restrict__ gamma,
                                             const float* __restrict__ beta,
                                             float* __restrict__ x) {
    int v = (blockIdx.x * blockDim.x + threadIdx.x) >> 5;
    int lane = threadIdx.x & 31;
    if (v >= NN) return;

    const __half2* h2 = (const __half2*)h;   // row stride 64 half2
    float a0 = 0.f, a1 = 0.f, a2 = 0.f, a3 = 0.f;
    float c0 = 0.f, c1 = 0.f, c2 = 0.f, c3 = 0.f;
    int beg = d_rowptr[s][v], end = d_rowptr[s][v + 1];
    float dv = d_dinv[s][v];

    int i = beg;
    for (; i + 2 <= end; i += 2) {
        int u0 = d_ssrc[s][i];
        int u1 = d_ssrc[s][i + 1];
        float w0 = d_dinv[s][u0];
        float w1 = d_dinv[s][u1];
        const __half2* p0 = h2 + (size_t)u0 * 64;
        const __half2* p1 = h2 + (size_t)u1 * 64;
        float2 q00 = __half22float2(p0[lane]);
        float2 q01 = __half22float2(p0[lane + 32]);
        float2 q10 = __half22float2(p1[lane]);
        float2 q11 = __half22float2(p1[lane + 32]);
        a0 += w0 * q00.x; a1 += w0 * q00.y; a2 += w0 * q01.x; a3 += w0 * q01.y;
        c0 += w1 * q10.x; c1 += w1 * q10.y; c2 += w1 * q11.x; c3 += w1 * q11.y;
    }
    if (i < end) {
        int u = d_ssrc[s][i];
        float w = d_dinv[s][u];
        const __half2* p = h2 + (size_t)u * 64;
        float2 q0 = __half22float2(p[lane]);
        float2 q1 = __half22float2(p[lane + 32]);
        a0 += w * q0.x; a1 += w * q0.y; a2 += w * q1.x; a3 += w * q1.y;
    }
    // self loop
    {
        const __half2* p = h2 + (size_t)v * 64;
        float2 q0 = __half22float2(p[lane]);
        float2 q1 = __half22float2(p[lane + 32]);
        a0 += c0 + dv * q0.x; a1 += c1 + dv * q0.y;
        a2 += c2 + dv * q1.x; a3 += c3 + dv * q1.y;
    }

    int ch0 = 2 * lane, ch2 = 64 + 2 * lane;
    a0 = a0 * dv + bias[ch0];
    a1 = a1 * dv + bias[ch0 + 1];
    a2 = a2 * dv + bias[ch2];
    a3 = a3 * dv + bias[ch2 + 1];

    float sum = a0 + a1 + a2 + a3;
    #pragma unroll
    for (int o = 16; o; o >>= 1) sum += __shfl_xor_sync(0xFFFFFFFFu, sum, o);
    float mu = sum * (1.f / HH);
    float v0 = a0 - mu, v1 = a1 - mu, v2 = a2 - mu, v3 = a3 - mu;
    float var = v0 * v0 + v1 * v1 + v2 * v2 + v3 * v3;
    #pragma unroll
    for (int o = 16; o; o >>= 1) var += __shfl_xor_sync(0xFFFFFFFFu, var, o);
    var *= (1.f / HH);
    float rstd = rsqrtf(var + LN_EPS);

    float2* xp = (float2*)(x + (size_t)v * HH);
    float2 r0 = xp[lane], r1 = xp[lane + 32];
    r0.x += fmaxf(v0 * rstd * gamma[ch0]     + beta[ch0],     0.f);
    r0.y += fmaxf(v1 * rstd * gamma[ch0 + 1] + beta[ch0 + 1], 0.f);
    r1.x += fmaxf(v2 * rstd * gamma[ch2]     + beta[ch2],     0.f);
    r1.y += fmaxf(v3 * rstd * gamma[ch2 + 1] + beta[ch2 + 1], 0.f);
    xp[lane] = r0;
    xp[lane + 32] = r1;
}

// ---------------- classifier ----------------
__global__ void __launch_bounds__(256) k_cls(const float* __restrict__ xr,
                                             const float* __restrict__ xv,
                                             const float* __restrict__ Wcls,
                                             const float* __restrict__ bcls,
                                             float* __restrict__ out) {
    __shared__ float WsT[CC * 2 * HH];
    __shared__ float bs[CC];
    for (int i = threadIdx.x; i < 2 * HH * CC; i += blockDim.x) {
        int k = i / CC, c = i % CC;
        WsT[c * (2 * HH) + k] = Wcls[i];
    }
    if (threadIdx.x < CC) bs[threadIdx.x] = bcls[threadIdx.x];
    __syncthreads();

    int v = (blockIdx.x * blockDim.x + threadIdx.x) >> 5;
    int lane = threadIdx.x & 31;
    if (v >= NN) return;

    float acc[CC];
    #pragma unroll
    for (int c = 0; c < CC; c++) acc[c] = 0.f;

    const float* a = xr + (size_t)v * HH;
    const float* b = xv + (size_t)v * HH;
    #pragma unroll
    for (int kk = 0; kk < 4; kk++) {
        int k = lane + 32 * kk;
        float av = a[k];
        float bv = b[k];
        #pragma unroll
        for (int c = 0; c < CC; c++) {
            acc[c] += av * WsT[c * (2 * HH) + k];
            acc[c] += bv * WsT[c * (2 * HH) + 128 + k];
        }
    }
    #pragma unroll
    for (int c = 0; c < CC; c++)
        #pragma unroll
        for (int o = 16; o; o >>= 1) acc[c] += __shfl_xor_sync(0xFFFFFFFFu, acc[c], o);

    if (lane == 0) {
        float* op = out + (size_t)v * CC;
        #pragma unroll
        for (int c = 0; c < CC; c++) op[c] = acc[c] + bs[c];
    }
}

// ---------------- driver ----------------
extern "C" void kernel_launch(void* const* d_in, const int* in_sizes, int n_in,
                              void* d_out, int out_size) {
    const float* x_in[2]  = { (const float*)d_in[0], (const float*)d_in[1] };
    const float* Wred[2]  = { (const float*)d_in[2], (const float*)d_in[4] };
    const float* bred[2]  = { (const float*)d_in[3], (const float*)d_in[5] };
    const float* W[2]     = { (const float*)d_in[6],  (const float*)d_in[10] };
    const float* b[2]     = { (const float*)d_in[7],  (const float*)d_in[11] };
    const float* g[2]     = { (const float*)d_in[8],  (const float*)d_in[12] };
    const float* be[2]    = { (const float*)d_in[9],  (const float*)d_in[13] };
    const float* Wcls     = (const float*)d_in[14];
    const float* bcls     = (const float*)d_in[15];
    const int*   ei[2]    = { (const int*)d_in[16], (const int*)d_in[17] };
    float* out = (float*)d_out;

    void* p;
    cudaGetSymbolAddress(&p, d_x);
    float* px = (float*)p;
    cudaGetSymbolAddress(&p, d_h);
    __half* ph = (__half*)p;
    __nv_bfloat16 *wredT_h, *wredT_l, *wT_h, *wT_l;
    cudaGetSymbolAddress(&p, d_wredT_h); wredT_h = (__nv_bfloat16*)p;
    cudaGetSymbolAddress(&p, d_wredT_l); wredT_l = (__nv_bfloat16*)p;
    cudaGetSymbolAddress(&p, d_wT_h);    wT_h    = (__nv_bfloat16*)p;
    cudaGetSymbolAddress(&p, d_wT_l);    wT_l    = (__nv_bfloat16*)p;

    const int THR = 256;
    const int blkN_node = (NN + THR - 1) / THR;
    const int blkE = (EE + THR - 1) / THR;
    const int blkWarp = (NN * 32 + THR - 1) / THR;
    const int blkGemm = (NN + 127) / 128;
    const int blkScan = (NN + 1023) / 1024;   // 49

    {
        const int TOT = 2 * (INDIM * HH + LLAYERS * HH * HH);
        k_prep<<<(TOT + THR - 1) / THR, THR>>>(Wred[0], Wred[1], W[0], W[1]);
    }

    for (int s = 0; s < 2; s++) {
        const int* src = ei[s];
        const int* dst = ei[s] + EE;
        float* xs = px + (size_t)s * NN * HH;

        k_zero<<<blkN_node, THR>>>(s);
        k_hist<<<blkE, THR>>>(dst, s);
        k_scan1<<<blkScan, 1024>>>(s);
        k_scan2<<<1, 64>>>();
        k_scan3<<<blkScan, 1024>>>(s);
        k_fill<<<blkE, THR>>>(src, dst, s);

        k_gemm_mma<INDIM, false><<<blkGemm, 256>>>(
            x_in[s], wredT_h + (size_t)s * HH * INDIM, wredT_l + (size_t)s * HH * INDIM,
            bred[s], xs, NN);

        for (int l = 0; l < LLAYERS; l++) {
            k_gemm_mma<HH, true><<<blkGemm, 256>>>(
                xs,
                wT_h + ((size_t)s * LLAYERS + l) * HH * HH,
                wT_l + ((size_t)s * LLAYERS + l) * HH * HH,
                nullptr, ph, NN);
            k_agg<<<blkWarp, THR>>>(ph, s, b[s] + l * HH, g[s] + l * HH, be[s] + l * HH, xs);
        }
    }

    k_cls<<<blkWarp, THR>>>(px, px + (size_t)NN * HH, Wcls, bcls, out);
}

// round 8
// speedup vs baseline: 1.9800x; 1.1476x over previous
#include <cuda_runtime.h>
#include <cuda_bf16.h>
#include <cuda_fp16.h>
#include <cstdint>

#define NN 50000
#define EE 800000
#define INDIM 256
#define HH 128
#define LLAYERS 4
#define CC 10
#define LN_EPS 1e-5f

// ---------------- scratch (device globals; no allocation) ----------------
__device__ int   d_indeg[2][NN];
__device__ int   d_rowptr[2][NN + 1];
__device__ int   d_cursor[2][NN];
__device__ float d_dinv[2][NN];
__device__ __align__(16) int2 d_edge[2][EE];      // {src, w_bits}
__device__ float d_x[2][(size_t)NN * HH];
__device__ __align__(16) __half d_h[2][(size_t)NN * HH];
__device__ int   d_blksum[2][64];

// pre-transposed, bf16-split weights: layout [n][k] (K-major rows of W^T)
__device__ __align__(16) __nv_bfloat16 d_wredT_h[2][HH * INDIM];
__device__ __align__(16) __nv_bfloat16 d_wredT_l[2][HH * INDIM];
__device__ __align__(16) __nv_bfloat16 d_wT_h[2][LLAYERS][HH * HH];
__device__ __align__(16) __nv_bfloat16 d_wT_l[2][LLAYERS][HH * HH];

// ---------------- PTX helpers ----------------
__device__ __forceinline__ uint32_t smem_u32(const void* p) {
    uint32_t a;
    asm("{ .reg .u64 t; cvta.to.shared.u64 t, %1; cvt.u32.u64 %0, t; }" : "=r"(a) : "l"(p));
    return a;
}

__device__ __forceinline__ void ldsm4(uint32_t* r, uint32_t addr) {
    asm volatile("ldmatrix.sync.aligned.m8n8.x4.shared.b16 {%0,%1,%2,%3}, [%4];"
                 : "=r"(r[0]), "=r"(r[1]), "=r"(r[2]), "=r"(r[3]) : "r"(addr));
}

__device__ __forceinline__ void mma16816(float* d, const uint32_t* a, const uint32_t* b) {
    asm volatile(
        "mma.sync.aligned.m16n8k16.row.col.f32.bf16.bf16.f32 "
        "{%0,%1,%2,%3}, {%4,%5,%6,%7}, {%8,%9}, {%0,%1,%2,%3};"
        : "+f"(d[0]), "+f"(d[1]), "+f"(d[2]), "+f"(d[3])
        : "r"(a[0]), "r"(a[1]), "r"(a[2]), "r"(a[3]), "r"(b[0]), "r"(b[1]));
}

#define CP_ASYNC16(dst, src) \
    asm volatile("cp.async.cg.shared.global [%0], [%1], 16;" :: "r"(dst), "l"(src))
#define CP_COMMIT() asm volatile("cp.async.commit_group;")
#define CP_WAIT0()  asm volatile("cp.async.wait_group 0;" ::: "memory")

// ---------------- CSR build (gridDim.y = 2 : both graph-streams per launch) ----
__global__ void k_zero() {
    int s = blockIdx.y;
    int i = blockIdx.x * blockDim.x + threadIdx.x;
    if (i < NN) d_indeg[s][i] = 0;
}

__global__ void k_hist(const int* __restrict__ dst0, const int* __restrict__ dst1) {
    int s = blockIdx.y;
    const int* dst = s ? dst1 : dst0;
    int e = blockIdx.x * blockDim.x + threadIdx.x;
    if (e < EE) atomicAdd(&d_indeg[s][dst[e]], 1);
}

__global__ void k_scan1() {
    __shared__ int sh[1024];
    int s = blockIdx.y;
    int b = blockIdx.x, t = threadIdx.x, i = b * 1024 + t;
    int v = (i < NN) ? d_indeg[s][i] : 0;
    sh[t] = v;
    __syncthreads();
    #pragma unroll
    for (int off = 1; off < 1024; off <<= 1) {
        int x = (t >= off) ? sh[t - off] : 0;
        __syncthreads();
        sh[t] += x;
        __syncthreads();
    }
    if (i < NN) {
        d_rowptr[s][i] = sh[t] - v;
        d_dinv[s][i]   = rsqrtf((float)(v + 1));
    }
    if (t == 1023) d_blksum[s][b] = sh[t];
}

__global__ void k_scan2() {
    __shared__ int sh[64];
    int s = blockIdx.y;
    int t = threadIdx.x;
    int v = (t < 49) ? d_blksum[s][t] : 0;
    sh[t] = v;
    __syncthreads();
    #pragma unroll
    for (int off = 1; off < 64; off <<= 1) {
        int x = (t >= off) ? sh[t - off] : 0;
        __syncthreads();
        sh[t] += x;
        __syncthreads();
    }
    if (t < 49) d_blksum[s][t] = sh[t] - v;
}

__global__ void k_scan3() {
    int s = blockIdx.y;
    int b = blockIdx.x, i = b * 1024 + threadIdx.x;
    if (i < NN) {
        int r = d_rowptr[s][i] + d_blksum[s][b];
        d_rowptr[s][i] = r;
        d_cursor[s][i] = r;
    }
    if (i == 0) d_rowptr[s][NN] = EE;
}

// fill packed edge records: {src, dinv[src]}
__global__ void k_fill(const int* __restrict__ src0, const int* __restrict__ dst0,
                       const int* __restrict__ src1, const int* __restrict__ dst1) {
    int s = blockIdx.y;
    const int* src = s ? src1 : src0;
    const int* dst = s ? dst1 : dst0;
    int e = blockIdx.x * blockDim.x + threadIdx.x;
    if (e < EE) {
        int u = src[e];
        int pos = atomicAdd(&d_cursor[s][dst[e]], 1);
        d_edge[s][pos] = make_int2(u, __float_as_int(d_dinv[s][u]));
    }
}

// ---------------- weight prep: transpose + bf16 hi/lo split ----------------
__global__ void k_prep(const float* __restrict__ Wred0, const float* __restrict__ Wred1,
                       const float* __restrict__ W0, const float* __restrict__ W1) {
    const int PER_STREAM = INDIM * HH + LLAYERS * HH * HH;
    int i = blockIdx.x * blockDim.x + threadIdx.x;
    if (i >= 2 * PER_STREAM) return;
    int s = i >= PER_STREAM;
    int j = i - s * PER_STREAM;
    float w;
    __nv_bfloat16 *ph, *pl;
    if (j < INDIM * HH) {
        int k = j >> 7, n = j & 127;
        w = (s ? Wred1 : Wred0)[k * HH + n];
        ph = &d_wredT_h[s][n * INDIM + k];
        pl = &d_wredT_l[s][n * INDIM + k];
    } else {
        int r = j - INDIM * HH;
        int l = r >> 14;
        int k = (r >> 7) & 127, n = r & 127;
        w = (s ? W1 : W0)[l * HH * HH + k * HH + n];
        ph = &d_wT_h[s][l][n * HH + k];
        pl = &d_wT_l[s][l][n * HH + k];
    }
    __nv_bfloat16 h = __float2bfloat16(w);
    *ph = h;
    *pl = __float2bfloat16(w - __bfloat162float(h));
}

// ---------------- mma.sync bf16 GEMM (3-pass compensated), batched over s ----
// gridDim = (391, 2). s = blockIdx.y selects stream.
template <int KTOT, bool HOUT>
__global__ void __launch_bounds__(256) k_gemm_mma(
    const float* __restrict__ A0, const float* __restrict__ A1,
    const float* __restrict__ bias0, const float* __restrict__ bias1,
    int l, int M)
{
    constexpr int RS = 80;
    __shared__ __align__(16) char smem[4 * 128 * RS];
    const uint32_t AS_H = smem_u32(smem);
    const uint32_t AS_L = AS_H + 128 * RS;
    const uint32_t BS_H = AS_H + 2 * 128 * RS;
    const uint32_t BS_L = AS_H + 3 * 128 * RS;

    int s = blockIdx.y;
    const float* A = s ? A1 : A0;
    const float* bias = s ? bias1 : bias0;
    const __nv_bfloat16* Bh = (KTOT == INDIM) ? d_wredT_h[s] : d_wT_h[s][l];
    const __nv_bfloat16* Bl = (KTOT == INDIM) ? d_wredT_l[s] : d_wT_l[s][l];

    int tid = threadIdx.x, w = tid >> 5, lane = tid & 31;
    int row0 = blockIdx.x * 128;
    int wm = (w >> 1) * 32, wn = (w & 1) * 64;

    float acc[2][8][4];
    #pragma unroll
    for (int i = 0; i < 2; i++)
        #pragma unroll
        for (int j = 0; j < 8; j++)
            #pragma unroll
            for (int q = 0; q < 4; q++) acc[i][j][q] = 0.f;

    int lrow = tid >> 1, lhalf = tid & 1;
    bool avalid = (row0 + lrow) < M;
    const float* aptr = A + (size_t)(row0 + lrow) * KTOT + lhalf * 16;
    const __nv_bfloat16* bhp = Bh + (size_t)lrow * KTOT + lhalf * 16;
    const __nv_bfloat16* blp = Bl + (size_t)lrow * KTOT + lhalf * 16;
    uint32_t ash_st = AS_H + lrow * RS + lhalf * 32;
    uint32_t asl_st = AS_L + lrow * RS + lhalf * 32;
    uint32_t bsh_st = BS_H + lrow * RS + lhalf * 32;
    uint32_t bsl_st = BS_L + lrow * RS + lhalf * 32;

    int a_r = lane & 15, a_k = (lane >> 4) * 8;
    int b_r = ((lane >> 4) << 3) + (lane & 7), b_k = ((lane >> 3) & 1) * 8;

    for (int c0 = 0; c0 < KTOT; c0 += 32) {
        CP_ASYNC16(bsh_st,      bhp);
        CP_ASYNC16(bsh_st + 16, bhp + 8);
        CP_ASYNC16(bsl_st,      blp);
        CP_ASYNC16(bsl_st + 16, blp + 8);
        CP_COMMIT();
        bhp += 32; blp += 32;

        float xv[16];
        if (avalid) {
            #pragma unroll
            for (int g = 0; g < 4; g++) {
                float4 v = *(const float4*)(aptr + g * 4);
                xv[g * 4] = v.x; xv[g * 4 + 1] = v.y; xv[g * 4 + 2] = v.z; xv[g * 4 + 3] = v.w;
            }
        } else {
            #pragma unroll
            for (int j = 0; j < 16; j++) xv[j] = 0.f;
        }
        aptr += 32;
        union { uint4 q[2]; __nv_bfloat16 b[16]; } hi, lo;
        #pragma unroll
        for (int j = 0; j < 16; j++) {
            __nv_bfloat16 h = __float2bfloat16(xv[j]);
            hi.b[j] = h;
            lo.b[j] = __float2bfloat16(xv[j] - __bfloat162float(h));
        }
        asm volatile("st.shared.v4.b32 [%0], {%1,%2,%3,%4};" :: "r"(ash_st),
            "r"(hi.q[0].x), "r"(hi.q[0].y), "r"(hi.q[0].z), "r"(hi.q[0].w));
        asm volatile("st.shared.v4.b32 [%0], {%1,%2,%3,%4};" :: "r"(ash_st + 16),
            "r"(hi.q[1].x), "r"(hi.q[1].y), "r"(hi.q[1].z), "r"(hi.q[1].w));
        asm volatile("st.shared.v4.b32 [%0], {%1,%2,%3,%4};" :: "r"(asl_st),
            "r"(lo.q[0].x), "r"(lo.q[0].y), "r"(lo.q[0].z), "r"(lo.q[0].w));
        asm volatile("st.shared.v4.b32 [%0], {%1,%2,%3,%4};" :: "r"(asl_st + 16),
            "r"(lo.q[1].x), "r"(lo.q[1].y), "r"(lo.q[1].z), "r"(lo.q[1].w));

        CP_WAIT0();
        __syncthreads();

        #pragma unroll
        for (int ks = 0; ks < 2; ks++) {
            int kb = ks * 16;
            uint32_t ah[2][4], al[2][4];
            #pragma unroll
            for (int mt = 0; mt < 2; mt++) {
                uint32_t off = (uint32_t)((wm + mt * 16 + a_r) * RS + (kb + a_k) * 2);
                ldsm4(ah[mt], AS_H + off);
                ldsm4(al[mt], AS_L + off);
            }
            uint32_t bh[4][4], bl[4][4];
            #pragma unroll
            for (int nt = 0; nt < 4; nt++) {
                uint32_t off = (uint32_t)((wn + nt * 16 + b_r) * RS + (kb + b_k) * 2);
                ldsm4(bh[nt], BS_H + off);
                ldsm4(bl[nt], BS_L + off);
            }
            #pragma unroll
            for (int mt = 0; mt < 2; mt++) {
                #pragma unroll
                for (int j = 0; j < 8; j++) {
                    const uint32_t* ph = &bh[j >> 1][(j & 1) * 2];
                    const uint32_t* pl = &bl[j >> 1][(j & 1) * 2];
                    mma16816(acc[mt][j], ah[mt], ph);
                    mma16816(acc[mt][j], ah[mt], pl);
                    mma16816(acc[mt][j], al[mt], ph);
                }
            }
        }
        __syncthreads();
    }

    int qr = lane >> 2, qc = (lane & 3) * 2;
    #pragma unroll
    for (int mt = 0; mt < 2; mt++) {
        int r0g = row0 + wm + mt * 16 + qr;
        #pragma unroll
        for (int j = 0; j < 8; j++) {
            int col = wn + j * 8 + qc;
            float b0 = 0.f, b1 = 0.f;
            if (bias) { b0 = bias[col]; b1 = bias[col + 1]; }
            if (HOUT) {
                __half* Ch = d_h[s];
                if (r0g < M)
                    *(__half2*)(Ch + (size_t)r0g * HH + col) =
                        __floats2half2_rn(acc[mt][j][0] + b0, acc[mt][j][1] + b1);
                if (r0g + 8 < M)
                    *(__half2*)(Ch + (size_t)(r0g + 8) * HH + col) =
                        __floats2half2_rn(acc[mt][j][2] + b0, acc[mt][j][3] + b1);
            } else {
                float* Cf = d_x[s];
                if (r0g < M)
                    *(float2*)(Cf + (size_t)r0g * HH + col) =
                        make_float2(acc[mt][j][0] + b0, acc[mt][j][1] + b1);
                if (r0g + 8 < M)
                    *(float2*)(Cf + (size_t)(r0g + 8) * HH + col) =
                        make_float2(acc[mt][j][2] + b0, acc[mt][j][3] + b1);
            }
        }
    }
}

// ---------------- fused GCN aggregate + bias + LayerNorm + ReLU + residual ----------------
// warp per node; h fp16; packed (src, w) edges; gridDim.y = 2.
__global__ void __launch_bounds__(256) k_agg(
    const float* __restrict__ b0p, const float* __restrict__ b1p,
    const float* __restrict__ g0p, const float* __restrict__ g1p,
    const float* __restrict__ e0p, const float* __restrict__ e1p,
    int l)
{
    int s = blockIdx.y;
    int v = (blockIdx.x * blockDim.x + threadIdx.x) >> 5;
    int lane = threadIdx.x & 31;
    if (v >= NN) return;

    const float* bias  = (s ? b1p : b0p) + l * HH;
    const float* gamma = (s ? g1p : g0p) + l * HH;
    const float* beta  = (s ? e1p : e0p) + l * HH;
    const __half2* h2 = (const __half2*)d_h[s];   // row stride 64 half2
    const int2* edges = d_edge[s];
    float* x = d_x[s];

    float a0 = 0.f, a1 = 0.f, a2 = 0.f, a3 = 0.f;
    float c0 = 0.f, c1 = 0.f, c2 = 0.f, c3 = 0.f;
    int beg = d_rowptr[s][v], end = d_rowptr[s][v + 1];
    float dv = d_dinv[s][v];

    int i = beg;
    for (; i + 2 <= end; i += 2) {
        int2 e0 = edges[i];
        int2 e1 = edges[i + 1];
        float w0 = __int_as_float(e0.y);
        float w1 = __int_as_float(e1.y);
        const __half2* p0 = h2 + (size_t)e0.x * 64;
        const __half2* p1 = h2 + (size_t)e1.x * 64;
        float2 q00 = __half22float2(p0[lane]);
        float2 q01 = __half22float2(p0[lane + 32]);
        float2 q10 = __half22float2(p1[lane]);
        float2 q11 = __half22float2(p1[lane + 32]);
        a0 += w0 * q00.x; a1 += w0 * q00.y; a2 += w0 * q01.x; a3 += w0 * q01.y;
        c0 += w1 * q10.x; c1 += w1 * q10.y; c2 += w1 * q11.x; c3 += w1 * q11.y;
    }
    if (i < end) {
        int2 e0 = edges[i];
        float w = __int_as_float(e0.y);
        const __half2* p = h2 + (size_t)e0.x * 64;
        float2 q0 = __half22float2(p[lane]);
        float2 q1 = __half22float2(p[lane + 32]);
        a0 += w * q0.x; a1 += w * q0.y; a2 += w * q1.x; a3 += w * q1.y;
    }
    {
        const __half2* p = h2 + (size_t)v * 64;
        float2 q0 = __half22float2(p[lane]);
        float2 q1 = __half22float2(p[lane + 32]);
        a0 += c0 + dv * q0.x; a1 += c1 + dv * q0.y;
        a2 += c2 + dv * q1.x; a3 += c3 + dv * q1.y;
    }

    int ch0 = 2 * lane, ch2 = 64 + 2 * lane;
    a0 = a0 * dv + bias[ch0];
    a1 = a1 * dv + bias[ch0 + 1];
    a2 = a2 * dv + bias[ch2];
    a3 = a3 * dv + bias[ch2 + 1];

    float sum = a0 + a1 + a2 + a3;
    #pragma unroll
    for (int o = 16; o; o >>= 1) sum += __shfl_xor_sync(0xFFFFFFFFu, sum, o);
    float mu = sum * (1.f / HH);
    float v0 = a0 - mu, v1 = a1 - mu, v2 = a2 - mu, v3 = a3 - mu;
    float var = v0 * v0 + v1 * v1 + v2 * v2 + v3 * v3;
    #pragma unroll
    for (int o = 16; o; o >>= 1) var += __shfl_xor_sync(0xFFFFFFFFu, var, o);
    var *= (1.f / HH);
    float rstd = rsqrtf(var + LN_EPS);

    float2* xp = (float2*)(x + (size_t)v * HH);
    float2 r0 = xp[lane], r1 = xp[lane + 32];
    r0.x += fmaxf(v0 * rstd * gamma[ch0]     + beta[ch0],     0.f);
    r0.y += fmaxf(v1 * rstd * gamma[ch0 + 1] + beta[ch0 + 1], 0.f);
    r1.x += fmaxf(v2 * rstd * gamma[ch2]     + beta[ch2],     0.f);
    r1.y += fmaxf(v3 * rstd * gamma[ch2 + 1] + beta[ch2 + 1], 0.f);
    xp[lane] = r0;
    xp[lane + 32] = r1;
}

// ---------------- classifier ----------------
__global__ void __launch_bounds__(256) k_cls(const float* __restrict__ Wcls,
                                             const float* __restrict__ bcls,
                                             float* __restrict__ out) {
    __shared__ float WsT[CC * 2 * HH];
    __shared__ float bs[CC];
    for (int i = threadIdx.x; i < 2 * HH * CC; i += blockDim.x) {
        int k = i / CC, c = i % CC;
        WsT[c * (2 * HH) + k] = Wcls[i];
    }
    if (threadIdx.x < CC) bs[threadIdx.x] = bcls[threadIdx.x];
    __syncthreads();

    int v = (blockIdx.x * blockDim.x + threadIdx.x) >> 5;
    int lane = threadIdx.x & 31;
    if (v >= NN) return;

    float acc[CC];
    #pragma unroll
    for (int c = 0; c < CC; c++) acc[c] = 0.f;

    const float* a = d_x[0] + (size_t)v * HH;
    const float* b = d_x[1] + (size_t)v * HH;
    #pragma unroll
    for (int kk = 0; kk < 4; kk++) {
        int k = lane + 32 * kk;
        float av = a[k];
        float bv = b[k];
        #pragma unroll
        for (int c = 0; c < CC; c++) {
            acc[c] += av * WsT[c * (2 * HH) + k];
            acc[c] += bv * WsT[c * (2 * HH) + 128 + k];
        }
    }
    #pragma unroll
    for (int c = 0; c < CC; c++)
        #pragma unroll
        for (int o = 16; o; o >>= 1) acc[c] += __shfl_xor_sync(0xFFFFFFFFu, acc[c], o);

    if (lane == 0) {
        float* op = out + (size_t)v * CC;
        #pragma unroll
        for (int c = 0; c < CC; c++) op[c] = acc[c] + bs[c];
    }
}

// ---------------- driver (single default stream — graph-capture safe) ----------------
extern "C" void kernel_launch(void* const* d_in, const int* in_sizes, int n_in,
                              void* d_out, int out_size) {
    const float* x_in[2]  = { (const float*)d_in[0], (const float*)d_in[1] };
    const float* Wred[2]  = { (const float*)d_in[2], (const float*)d_in[4] };
    const float* bred[2]  = { (const float*)d_in[3], (const float*)d_in[5] };
    const float* W[2]     = { (const float*)d_in[6],  (const float*)d_in[10] };
    const float* b[2]     = { (const float*)d_in[7],  (const float*)d_in[11] };
    const float* g[2]     = { (const float*)d_in[8],  (const float*)d_in[12] };
    const float* be[2]    = { (const float*)d_in[9],  (const float*)d_in[13] };
    const float* Wcls     = (const float*)d_in[14];
    const float* bcls     = (const float*)d_in[15];
    const int*   ei[2]    = { (const int*)d_in[16], (const int*)d_in[17] };
    float* out = (float*)d_out;

    void* p0;
    cudaGetSymbolAddress(&p0, d_x);
    float* px = (float*)p0;

    const int THR = 256;
    const dim3 gN((NN + THR - 1) / THR, 2);
    const dim3 gE((EE + THR - 1) / THR, 2);
    const dim3 gW((NN * 32 + THR - 1) / THR, 2);
    const dim3 gG((NN + 127) / 128, 2);
    const dim3 gS((NN + 1023) / 1024, 2);
    const dim3 gS2(1, 2);
    const int blkWarp1 = (NN * 32 + THR - 1) / THR;

    {
        const int TOT = 2 * (INDIM * HH + LLAYERS * HH * HH);
        k_prep<<<(TOT + THR - 1) / THR, THR>>>(Wred[0], Wred[1], W[0], W[1]);
    }

    // CSR build (both streams per launch)
    k_zero<<<gN, THR>>>();
    k_hist<<<gE, THR>>>(ei[0] + EE, ei[1] + EE);
    k_scan1<<<gS, 1024>>>();
    k_scan2<<<gS2, 64>>>();
    k_scan3<<<gS, 1024>>>();
    k_fill<<<gE, THR>>>(ei[0], ei[0] + EE, ei[1], ei[1] + EE);

    // dim-reduction GEMM (both streams)
    k_gemm_mma<INDIM, false><<<gG, 256>>>(x_in[0], x_in[1], bred[0], bred[1], 0, NN);

    // 4 layers (both streams per launch)
    for (int l = 0; l < LLAYERS; l++) {
        k_gemm_mma<HH, true><<<gG, 256>>>(px, px + (size_t)NN * HH, nullptr, nullptr, l, NN);
        k_agg<<<gW, THR>>>(b[0], b[1], g[0], g[1], be[0], be[1], l);
    }

    k_cls<<<blkWarp1, THR>>>(Wcls, bcls, out);
}